// round 1
// baseline (speedup 1.0000x reference)
#include <cuda_runtime.h>

#define BB 4
#define CC 64
#define HH 256
#define WW 256
#define HW (HH*WW)
#define CHW (CC*HW)

#define SIGMA_MIN 0.6f
#define SIGMA_MAX 1.2f

// Scratch (static device allocations — no cudaMalloc allowed)
__device__ float d_edge[BB*HW];          // 1 MB
__device__ float d_g[4][BB*HW];          // 4 MB (symmetric taps: w0,w1,w2,center)
__device__ float d_tmp[(size_t)BB*CHW];  // 64 MB horizontal-pass result
__device__ unsigned int d_minmax[2*BB];  // per-batch {min,max} as uint bits (edge>=0)

__global__ void init_minmax_kernel() {
    int i = threadIdx.x;
    if (i < BB) {
        d_minmax[2*i]   = 0x7f800000u; // +inf
        d_minmax[2*i+1] = 0u;          // 0
    }
}

// Sobel edge magnitude, mean over channels; fused per-batch min/max reduction.
// Block = 32x8 pixel tile, loops over 64 channels.
__global__ void edge_kernel(const float* __restrict__ x) {
    const int w = blockIdx.x*32 + threadIdx.x;
    const int h = blockIdx.y*8  + threadIdx.y;
    const int b = blockIdx.z;

    const float* p0 = x + (size_t)b*CHW + h*WW + w;
    const bool hm = (h > 0), hp = (h < HH-1);
    const bool wm = (w > 0), wp = (w < WW-1);

    float acc = 0.f;
    #pragma unroll 4
    for (int c = 0; c < CC; c++) {
        const float* p = p0 + c*HW;
        float a00 = (hm && wm) ? p[-WW-1] : 0.f;
        float a01 =  hm        ? p[-WW]   : 0.f;
        float a02 = (hm && wp) ? p[-WW+1] : 0.f;
        float a10 =  wm        ? p[-1]    : 0.f;
        float a12 =  wp        ? p[ 1]    : 0.f;
        float a20 = (hp && wm) ? p[ WW-1] : 0.f;
        float a21 =  hp        ? p[ WW]   : 0.f;
        float a22 = (hp && wp) ? p[ WW+1] : 0.f;
        float gx = (a02 - a00) + 2.f*(a12 - a10) + (a22 - a20);
        float gy = (a20 - a00) + 2.f*(a21 - a01) + (a22 - a02);
        acc = fmaf(gx, gx, acc);
        acc = fmaf(gy, gy, acc);
    }
    const float edge = acc * (1.f/64.f);
    d_edge[b*HW + h*WW + w] = edge;

    // block min/max -> atomics (uint ordering valid for non-negative floats)
    float vmin = edge, vmax = edge;
    #pragma unroll
    for (int o = 16; o; o >>= 1) {
        vmin = fminf(vmin, __shfl_xor_sync(0xffffffffu, vmin, o));
        vmax = fmaxf(vmax, __shfl_xor_sync(0xffffffffu, vmax, o));
    }
    __shared__ float smin[8], smax[8];
    if (threadIdx.x == 0) { smin[threadIdx.y] = vmin; smax[threadIdx.y] = vmax; }
    __syncthreads();
    if (threadIdx.x == 0 && threadIdx.y == 0) {
        float m = smin[0], M = smax[0];
        #pragma unroll
        for (int i = 1; i < 8; i++) { m = fminf(m, smin[i]); M = fmaxf(M, smax[i]); }
        atomicMin(&d_minmax[2*b],   __float_as_uint(m));
        atomicMax(&d_minmax[2*b+1], __float_as_uint(M));
    }
}

// Per-pixel normalized Gaussian taps (symmetric: store 4 planes).
__global__ void gauss_kernel() {
    const int idx = blockIdx.x*blockDim.x + threadIdx.x;
    const int b = idx / HW;
    const float emin = __uint_as_float(d_minmax[2*b]);
    const float emax = __uint_as_float(d_minmax[2*b+1]);
    const float e = (d_edge[idx] - emin) / (emax + 1e-6f);
    const float s = SIGMA_MIN + (SIGMA_MAX - SIGMA_MIN)*e;
    const float inv = 0.5f / (s*s);
    const float w2 = __expf(-1.f*inv);
    const float w1 = __expf(-4.f*inv);
    const float w0 = __expf(-9.f*inv);
    const float r = 1.f / (2.f*(w0 + w1 + w2) + 1.f);
    d_g[0][idx] = w0*r;
    d_g[1][idx] = w1*r;
    d_g[2][idx] = w2*r;
    d_g[3][idx] = r;
}

// Horizontal pass: block = one (b,h) row, g in registers, channel loop via smem row.
__global__ void hblur_kernel(const float* __restrict__ x) {
    const int w = threadIdx.x;
    const int h = blockIdx.x;
    const int b = blockIdx.y;
    const int pidx = b*HW + h*WW + w;

    const float g0 = d_g[0][pidx];
    const float g1 = d_g[1][pidx];
    const float g2 = d_g[2][pidx];
    const float g3 = d_g[3][pidx];

    __shared__ float row[WW + 6];
    if (w < 3)       row[w]     = 0.f;   // left zero pad
    if (w >= WW - 3) row[w + 6] = 0.f;   // right zero pad

    const float* xb = x     + (size_t)b*CHW + h*WW;
    float*       tb = d_tmp + (size_t)b*CHW + h*WW;

    for (int c = 0; c < CC; c++) {
        row[w + 3] = xb[c*HW + w];
        __syncthreads();
        float v = g3 * row[w + 3];
        v = fmaf(g2, row[w + 2] + row[w + 4], v);
        v = fmaf(g1, row[w + 1] + row[w + 5], v);
        v = fmaf(g0, row[w]     + row[w + 6], v);
        tb[c*HW + w] = v;
        __syncthreads();
    }
}

// Vertical pass: 32x8 tile, g in registers, channel loop; tmp mostly L2-resident.
__global__ void vblur_kernel(float* __restrict__ out) {
    const int w = blockIdx.x*32 + threadIdx.x;
    const int h = blockIdx.y*8  + threadIdx.y;
    const int b = blockIdx.z;
    const int pidx = b*HW + h*WW + w;

    const float g0 = d_g[0][pidx];
    const float g1 = d_g[1][pidx];
    const float g2 = d_g[2][pidx];
    const float g3 = d_g[3][pidx];

    const float* tb = d_tmp + (size_t)b*CHW + h*WW + w;
    float*       ob = out   + (size_t)b*CHW + h*WW + w;

    if (h >= 3 && h < HH-3) {
        #pragma unroll 2
        for (int c = 0; c < CC; c++) {
            const float* p = tb + c*HW;
            float v = g3 * p[0];
            v = fmaf(g2, p[-WW]   + p[WW],   v);
            v = fmaf(g1, p[-2*WW] + p[2*WW], v);
            v = fmaf(g0, p[-3*WW] + p[3*WW], v);
            ob[c*HW] = v;
        }
    } else {
        const bool m1 = (h >= 1), m2 = (h >= 2), m3 = (h >= 3);
        const bool p1 = (h < HH-1), p2 = (h < HH-2), p3 = (h < HH-3);
        for (int c = 0; c < CC; c++) {
            const float* p = tb + c*HW;
            float u1 = m1 ? p[-WW]   : 0.f, d1 = p1 ? p[WW]   : 0.f;
            float u2 = m2 ? p[-2*WW] : 0.f, d2 = p2 ? p[2*WW] : 0.f;
            float u3 = m3 ? p[-3*WW] : 0.f, d3 = p3 ? p[3*WW] : 0.f;
            float v = g3 * p[0];
            v = fmaf(g2, u1 + d1, v);
            v = fmaf(g1, u2 + d2, v);
            v = fmaf(g0, u3 + d3, v);
            ob[c*HW] = v;
        }
    }
}

extern "C" void kernel_launch(void* const* d_in, const int* in_sizes, int n_in,
                              void* d_out, int out_size) {
    const float* x = (const float*)d_in[0];
    float* out = (float*)d_out;

    init_minmax_kernel<<<1, 32>>>();

    dim3 tile(32, 8);
    edge_kernel<<<dim3(WW/32, HH/8, BB), tile>>>(x);

    gauss_kernel<<<(BB*HW)/256, 256>>>();

    hblur_kernel<<<dim3(HH, BB), WW>>>(x);

    vblur_kernel<<<dim3(WW/32, HH/8, BB), tile>>>(out);
}